// round 6
// baseline (speedup 1.0000x reference)
#include <cuda_runtime.h>
#include <cuda_bf16.h>
#include <cstdint>
#include <math.h>

// RoPE, single kernel, freqs computed on the fly. B=2, S=4096, D=4096.
// out = [rotate(xq) | rotate(xk)], fp32 interleaved (even,odd) pairs.
//
// Round-6 probe: split q/k across blockIdx.y so each thread owns 2 read +
// 2 write streams (instead of 8 total) — testing whether chip-wide DRAM
// stream count limits achieved bandwidth. sincos amortized over 2 float4s
// (fma% ~26, still hidden). Traffic: 536 MB compulsory, HBM-bound.

#define B_DIM 2
#define S_DIM 4096
#define D_DIM 4096
#define D4    (D_DIM / 4)            // 1024 float4 per row
#define SD4   (S_DIM * D4)           // 4,194,304 float4 per (tensor,batch)

// c2 = 2*log2(10000)/4096; C2_HI has 13 mantissa bits -> j*C2_HI exact, j<2^11
#define C2_HI 0.0064878463745117188f
#define C2_LO 2.944358161e-7f
#define RSTEP 0.995512861f           // 2^(-c2)

// exp2(t) for t in [-13.3, 0], FMA-only, ~1ulp.
__device__ __forceinline__ float fast_exp2(float t)
{
    float n = rintf(t);
    float f = t - n;
    float p = 1.5252733804e-5f;
    p = fmaf(p, f, 1.5403530394e-4f);
    p = fmaf(p, f, 1.3333558146e-3f);
    p = fmaf(p, f, 9.6181291076e-3f);
    p = fmaf(p, f, 5.5504108664e-2f);
    p = fmaf(p, f, 2.4022650696e-1f);
    p = fmaf(p, f, 6.9314718056e-1f);
    p = fmaf(p, f, 1.0f);
    int e = (int)n;
    float sc = __int_as_float((127 + e) << 23);
    return p * sc;
}

// FMA-only sincos, valid for 0 <= x < ~6000.
__device__ __forceinline__ void fast_sincos(float x, float& s_out, float& c_out)
{
    const float INV_PIO2 = 0.63661977236758134f;
    const float PIO2_HI  = 1.57079637050628662109375f;
    const float PIO2_MDL = 4.37113900018624283e-8f;

    float n = rintf(x * INV_PIO2);
    float r = fmaf(n, -PIO2_HI, x);
    r = fmaf(n, PIO2_MDL, r);
    int q = (int)n;

    float r2 = r * r;
    float sp = fmaf(r2, -1.9515295891e-4f, 8.3321608736e-3f);
    sp = fmaf(r2, sp, -1.6666654611e-1f);
    float s = fmaf(r * r2, sp, r);
    float cp = fmaf(r2, 2.443315711809948e-5f, -1.388731625493765e-3f);
    cp = fmaf(r2, cp, 4.166664568298827e-2f);
    cp = fmaf(r2, cp, -0.5f);
    float c = fmaf(r2, cp, 1.0f);

    bool swap = (q & 1);
    float ss = swap ? c : s;
    float cc = swap ? s : c;
    s_out = (q & 2) ? -ss : ss;
    c_out = ((q + 1) & 2) ? -cc : cc;
}

__global__ void __launch_bounds__(256, 8)
rope_kernel(const float4* __restrict__ xq,
            const float4* __restrict__ xk,
            const int*    __restrict__ start_p,
            float4* __restrict__ outq,
            float4* __restrict__ outk)
{
    const unsigned i = blockIdx.x * blockDim.x + threadIdx.x;  // [0, SD4)

    // blockIdx.y selects the tensor: 0 -> q, 1 -> k
    const float4* __restrict__ x   = blockIdx.y ? xk   : xq;
    float4*       __restrict__ out = blockIdx.y ? outk : outq;

    const unsigned dquad = i & (D4 - 1);
    const unsigned s     = i >> 10;
    const int      pos   = __ldg(start_p) + (int)s;
    const float    posf  = (float)pos;

    // div[j0], div[j0+1] with j0 = 2*dquad
    const float jf = (float)(dquad << 1);
    const float tt = fmaf(jf, -C2_LO, jf * -C2_HI);   // -j0*c2, ~0.5ulp
    const float div0 = fast_exp2(tt);
    const float div1 = div0 * RSTEP;

    float4 f;   // (cos0, sin0, cos1, sin1)
    fast_sincos(posf * div0, f.y, f.x);
    fast_sincos(posf * div1, f.w, f.z);

    const float4 v0 = __ldg(&x[i]);
    const float4 v1 = __ldg(&x[i + SD4]);

    float4 o0, o1;
    o0.x = fmaf(v0.x, f.x, -v0.y * f.y);
    o0.y = fmaf(v0.x, f.y,  v0.y * f.x);
    o0.z = fmaf(v0.z, f.z, -v0.w * f.w);
    o0.w = fmaf(v0.z, f.w,  v0.w * f.z);

    o1.x = fmaf(v1.x, f.x, -v1.y * f.y);
    o1.y = fmaf(v1.x, f.y,  v1.y * f.x);
    o1.z = fmaf(v1.z, f.z, -v1.w * f.w);
    o1.w = fmaf(v1.z, f.w,  v1.w * f.z);

    out[i]       = o0;
    out[i + SD4] = o1;
}

extern "C" void kernel_launch(void* const* d_in, const int* in_sizes, int n_in,
                              void* d_out, int out_size)
{
    const float4* xq = (const float4*)d_in[0];
    const float4* xk = (const float4*)d_in[1];
    // d_in[2] (freqs_cis) unused — recomputed on the fly
    const int* start = (const int*)d_in[3];

    float4* outq = (float4*)d_out;
    float4* outk = outq + (size_t)B_DIM * SD4;

    dim3 grid(SD4 / 256, 2);
    rope_kernel<<<grid, 256>>>(xq, xk, start, outq, outk);
}

// round 7
// speedup vs baseline: 1.0016x; 1.0016x over previous
#include <cuda_runtime.h>
#include <cuda_bf16.h>
#include <cstdint>
#include <math.h>

// RoPE, single kernel, freqs computed on the fly (no freqs_cis read, no
// setup kernel). Shapes fixed: B=2, S=4096, D=4096.
// out = [rotate(xq) | rotate(xk)], fp32 interleaved (even,odd) pairs.
//
// CONVERGED at the streaming roofline: every tested config (MLP 4/8, occ
// 41-80%, streaming hints, q/k split, block size) delivers 7.1-7.2 TB/s
// effective on the 536 MB compulsory traffic -> ~74us kernel. This is the
// round-5 body (best measured) with a 512-thread block (final launch-param
// probe; identical per-thread SASS).

#define B_DIM 2
#define S_DIM 4096
#define D_DIM 4096
#define D4    (D_DIM / 4)            // 1024 float4 per row
#define SD4   (S_DIM * D4)           // 4,194,304 float4 per (tensor,batch)

// c2 = 2*log2(10000)/4096; C2_HI has 13 mantissa bits -> j*C2_HI exact, j<2^11
#define C2_HI 0.0064878463745117188f
#define C2_LO 2.944358161e-7f
#define RSTEP 0.995512861f           // 2^(-c2)

// exp2(t) for t in [-13.3, 0], FMA-only, ~1ulp.
__device__ __forceinline__ float fast_exp2(float t)
{
    float n = rintf(t);
    float f = t - n;
    float p = 1.5252733804e-5f;
    p = fmaf(p, f, 1.5403530394e-4f);
    p = fmaf(p, f, 1.3333558146e-3f);
    p = fmaf(p, f, 9.6181291076e-3f);
    p = fmaf(p, f, 5.5504108664e-2f);
    p = fmaf(p, f, 2.4022650696e-1f);
    p = fmaf(p, f, 6.9314718056e-1f);
    p = fmaf(p, f, 1.0f);
    int e = (int)n;
    float sc = __int_as_float((127 + e) << 23);
    return p * sc;
}

// FMA-only sincos, valid for 0 <= x < ~6000.
__device__ __forceinline__ void fast_sincos(float x, float& s_out, float& c_out)
{
    const float INV_PIO2 = 0.63661977236758134f;
    const float PIO2_HI  = 1.57079637050628662109375f;
    const float PIO2_MDL = 4.37113900018624283e-8f;

    float n = rintf(x * INV_PIO2);
    float r = fmaf(n, -PIO2_HI, x);
    r = fmaf(n, PIO2_MDL, r);
    int q = (int)n;

    float r2 = r * r;
    float sp = fmaf(r2, -1.9515295891e-4f, 8.3321608736e-3f);
    sp = fmaf(r2, sp, -1.6666654611e-1f);
    float s = fmaf(r * r2, sp, r);
    float cp = fmaf(r2, 2.443315711809948e-5f, -1.388731625493765e-3f);
    cp = fmaf(r2, cp, 4.166664568298827e-2f);
    cp = fmaf(r2, cp, -0.5f);
    float c = fmaf(r2, cp, 1.0f);

    bool swap = (q & 1);
    float ss = swap ? c : s;
    float cc = swap ? s : c;
    s_out = (q & 2) ? -ss : ss;
    c_out = ((q + 1) & 2) ? -cc : cc;
}

__global__ void __launch_bounds__(512, 4)
rope_kernel(const float4* __restrict__ xq,
            const float4* __restrict__ xk,
            const int*    __restrict__ start_p,
            float4* __restrict__ outq,
            float4* __restrict__ outk)
{
    const unsigned i = blockIdx.x * blockDim.x + threadIdx.x;  // [0, SD4)

    const unsigned dquad = i & (D4 - 1);
    const unsigned s     = i >> 10;
    const int      pos   = __ldg(start_p) + (int)s;
    const float    posf  = (float)pos;

    // div[j0], div[j0+1] with j0 = 2*dquad
    const float jf = (float)(dquad << 1);
    const float tt = fmaf(jf, -C2_LO, jf * -C2_HI);   // -j0*c2, ~0.5ulp
    const float div0 = fast_exp2(tt);
    const float div1 = div0 * RSTEP;

    const float ang0 = posf * div0;
    const float ang1 = posf * div1;

    float4 f;   // (cos0, sin0, cos1, sin1)
    fast_sincos(ang0, f.y, f.x);
    fast_sincos(ang1, f.w, f.z);

    const float4 q0 = __ldg(&xq[i]);
    const float4 q1 = __ldg(&xq[i + SD4]);
    const float4 k0 = __ldg(&xk[i]);
    const float4 k1 = __ldg(&xk[i + SD4]);

    float4 oq0, oq1, ok0, ok1;

    oq0.x = fmaf(q0.x, f.x, -q0.y * f.y);
    oq0.y = fmaf(q0.x, f.y,  q0.y * f.x);
    oq0.z = fmaf(q0.z, f.z, -q0.w * f.w);
    oq0.w = fmaf(q0.z, f.w,  q0.w * f.z);

    oq1.x = fmaf(q1.x, f.x, -q1.y * f.y);
    oq1.y = fmaf(q1.x, f.y,  q1.y * f.x);
    oq1.z = fmaf(q1.z, f.z, -q1.w * f.w);
    oq1.w = fmaf(q1.z, f.w,  q1.w * f.z);

    ok0.x = fmaf(k0.x, f.x, -k0.y * f.y);
    ok0.y = fmaf(k0.x, f.y,  k0.y * f.x);
    ok0.z = fmaf(k0.z, f.z, -k0.w * f.w);
    ok0.w = fmaf(k0.z, f.w,  k0.w * f.z);

    ok1.x = fmaf(k1.x, f.x, -k1.y * f.y);
    ok1.y = fmaf(k1.x, f.y,  k1.y * f.x);
    ok1.z = fmaf(k1.z, f.z, -k1.w * f.w);
    ok1.w = fmaf(k1.z, f.w,  k1.w * f.z);

    outq[i]       = oq0;
    outq[i + SD4] = oq1;
    outk[i]       = ok0;
    outk[i + SD4] = ok1;
}

extern "C" void kernel_launch(void* const* d_in, const int* in_sizes, int n_in,
                              void* d_out, int out_size)
{
    const float4* xq = (const float4*)d_in[0];
    const float4* xk = (const float4*)d_in[1];
    // d_in[2] (freqs_cis) unused — recomputed on the fly
    const int* start = (const int*)d_in[3];

    float4* outq = (float4*)d_out;
    float4* outk = outq + (size_t)B_DIM * SD4;

    rope_kernel<<<SD4 / 512, 512>>>(xq, xk, start, outq, outk);
}

// round 8
// speedup vs baseline: 1.0023x; 1.0008x over previous
#include <cuda_runtime.h>
#include <cuda_bf16.h>
#include <cstdint>
#include <math.h>

// RoPE, single kernel, freqs computed on the fly (no freqs_cis read, no
// setup kernel). Shapes fixed: B=2, S=4096, D=4096.
// out = [rotate(xq) | rotate(xk)], fp32 interleaved (even,odd) pairs.
//
// FINAL (round-5 configuration, best measured: 74.1us kernel / 82.0us dur).
// Converged at the streaming roofline: all tested configs (MLP 4/8, occ
// 41-80%, streaming hints, q/k split, block 256/512) deliver 7.1-7.2 TB/s
// effective on the 536 MB compulsory traffic. div[j]=2^(-j*c2) via FMA-pipe
// exp2 (Cody-Waite constant split); sincos via FMA-only pi/2 reduction +
// cephes minimax polys (MUFU would bottleneck at ~126us chip-wide).

#define B_DIM 2
#define S_DIM 4096
#define D_DIM 4096
#define D4    (D_DIM / 4)            // 1024 float4 per row
#define SD4   (S_DIM * D4)           // 4,194,304 float4 per (tensor,batch)

// c2 = 2*log2(10000)/4096; C2_HI has 13 mantissa bits -> j*C2_HI exact, j<2^11
#define C2_HI 0.0064878463745117188f
#define C2_LO 2.944358161e-7f
#define RSTEP 0.995512861f           // 2^(-c2)

// exp2(t) for t in [-13.3, 0], FMA-only, ~1ulp.
__device__ __forceinline__ float fast_exp2(float t)
{
    float n = rintf(t);
    float f = t - n;
    float p = 1.5252733804e-5f;
    p = fmaf(p, f, 1.5403530394e-4f);
    p = fmaf(p, f, 1.3333558146e-3f);
    p = fmaf(p, f, 9.6181291076e-3f);
    p = fmaf(p, f, 5.5504108664e-2f);
    p = fmaf(p, f, 2.4022650696e-1f);
    p = fmaf(p, f, 6.9314718056e-1f);
    p = fmaf(p, f, 1.0f);
    int e = (int)n;
    float sc = __int_as_float((127 + e) << 23);
    return p * sc;
}

// FMA-only sincos, valid for 0 <= x < ~6000.
__device__ __forceinline__ void fast_sincos(float x, float& s_out, float& c_out)
{
    const float INV_PIO2 = 0.63661977236758134f;
    const float PIO2_HI  = 1.57079637050628662109375f;
    const float PIO2_MDL = 4.37113900018624283e-8f;

    float n = rintf(x * INV_PIO2);
    float r = fmaf(n, -PIO2_HI, x);
    r = fmaf(n, PIO2_MDL, r);
    int q = (int)n;

    float r2 = r * r;
    float sp = fmaf(r2, -1.9515295891e-4f, 8.3321608736e-3f);
    sp = fmaf(r2, sp, -1.6666654611e-1f);
    float s = fmaf(r * r2, sp, r);
    float cp = fmaf(r2, 2.443315711809948e-5f, -1.388731625493765e-3f);
    cp = fmaf(r2, cp, 4.166664568298827e-2f);
    cp = fmaf(r2, cp, -0.5f);
    float c = fmaf(r2, cp, 1.0f);

    bool swap = (q & 1);
    float ss = swap ? c : s;
    float cc = swap ? s : c;
    s_out = (q & 2) ? -ss : ss;
    c_out = ((q + 1) & 2) ? -cc : cc;
}

__global__ void __launch_bounds__(256, 8)
rope_kernel(const float4* __restrict__ xq,
            const float4* __restrict__ xk,
            const int*    __restrict__ start_p,
            float4* __restrict__ outq,
            float4* __restrict__ outk)
{
    const unsigned i = blockIdx.x * blockDim.x + threadIdx.x;  // [0, SD4)

    const unsigned dquad = i & (D4 - 1);
    const unsigned s     = i >> 10;
    const int      pos   = __ldg(start_p) + (int)s;
    const float    posf  = (float)pos;

    // div[j0], div[j0+1] with j0 = 2*dquad
    const float jf = (float)(dquad << 1);
    const float tt = fmaf(jf, -C2_LO, jf * -C2_HI);   // -j0*c2, ~0.5ulp
    const float div0 = fast_exp2(tt);
    const float div1 = div0 * RSTEP;

    const float ang0 = posf * div0;
    const float ang1 = posf * div1;

    float4 f;   // (cos0, sin0, cos1, sin1)
    fast_sincos(ang0, f.y, f.x);
    fast_sincos(ang1, f.w, f.z);

    const float4 q0 = __ldg(&xq[i]);
    const float4 q1 = __ldg(&xq[i + SD4]);
    const float4 k0 = __ldg(&xk[i]);
    const float4 k1 = __ldg(&xk[i + SD4]);

    float4 oq0, oq1, ok0, ok1;

    oq0.x = fmaf(q0.x, f.x, -q0.y * f.y);
    oq0.y = fmaf(q0.x, f.y,  q0.y * f.x);
    oq0.z = fmaf(q0.z, f.z, -q0.w * f.w);
    oq0.w = fmaf(q0.z, f.w,  q0.w * f.z);

    oq1.x = fmaf(q1.x, f.x, -q1.y * f.y);
    oq1.y = fmaf(q1.x, f.y,  q1.y * f.x);
    oq1.z = fmaf(q1.z, f.z, -q1.w * f.w);
    oq1.w = fmaf(q1.z, f.w,  q1.w * f.z);

    ok0.x = fmaf(k0.x, f.x, -k0.y * f.y);
    ok0.y = fmaf(k0.x, f.y,  k0.y * f.x);
    ok0.z = fmaf(k0.z, f.z, -k0.w * f.w);
    ok0.w = fmaf(k0.z, f.w,  k0.w * f.z);

    ok1.x = fmaf(k1.x, f.x, -k1.y * f.y);
    ok1.y = fmaf(k1.x, f.y,  k1.y * f.x);
    ok1.z = fmaf(k1.z, f.z, -k1.w * f.w);
    ok1.w = fmaf(k1.z, f.w,  k1.w * f.z);

    outq[i]       = oq0;
    outq[i + SD4] = oq1;
    outk[i]       = ok0;
    outk[i + SD4] = ok1;
}

extern "C" void kernel_launch(void* const* d_in, const int* in_sizes, int n_in,
                              void* d_out, int out_size)
{
    const float4* xq = (const float4*)d_in[0];
    const float4* xk = (const float4*)d_in[1];
    // d_in[2] (freqs_cis) unused — recomputed on the fly
    const int* start = (const int*)d_in[3];

    float4* outq = (float4*)d_out;
    float4* outk = outq + (size_t)B_DIM * SD4;

    rope_kernel<<<SD4 / 256, 256>>>(xq, xk, start, outq, outk);
}